// round 15
// baseline (speedup 1.0000x reference)
#include <cuda_runtime.h>
#include <cuda_fp16.h>

#define NN 50000
#define EE 1600000
#define E2 (EE + NN)
#define H 4
#define C 16
#define D 64
#define SB 512
#define NB ((NN + SB - 1) / SB)        // 98
#define STATS_BLKS (EE / 256)          // 6250 exact
#define SCAT_BLKS ((E2 + 255) / 256)   // 6446
#define NPB 64
#define GEMM_BLKS ((NN + NPB - 1) / NPB)  // 782
#define AGG_BLKS (NN / 8)              // 6250
#define ZERO_BLKS 196

// ---------------- scratch (static device globals; no allocation) -------------
// g_icnt / g_loop are zeroed at the TAIL of each call (agg layer 1), so every
// call finds them zero. Module load zero-initializes for the first call.
__device__ int   g_icnt[NN];
__device__ float g_loop[NN];
__device__ int   g_rowptr[NN + 1];
__device__ int   g_cursor[NN];
__device__ int   g_bsum[NB];
__device__ int   g_boff[NB];
__device__ int2  g_epack[E2];                         // {src, float_bits(ea)}
__device__ __align__(16) __half2 g_xsh1[NN * 32];     // layer-1 messages (fp16)
__device__ __align__(16) __half2 g_xsh2[NN * 32];     // layer-2 messages (fp16)
__device__ __align__(16) float g_as1[NN * H];
__device__ __align__(16) float g_ad1[NN * H];
__device__ __align__(16) float g_as2[NN * H];
__device__ __align__(16) float g_ad2[NN * H];
__device__ __align__(16) float g_h1[NN * D];
__device__ float4 g_wedot4[2];

// ---------------- GEMM body (layer 1): xs = x @ W1 + per-head attn dots ------
// 256 threads: 16 node-quads x 16 feature-quads; thread owns 4x4 outputs.
__device__ __forceinline__ void gemm_body(
    const float* __restrict__ x, const float* __restrict__ W,
    const float* __restrict__ as, const float* __restrict__ ad,
    int blk, float* smem) {
    float* Ws = smem;                 // D*D floats
    float* xr = smem + D * D;         // NPB*68 floats (17 float4 stride)
    int tid = threadIdx.x;
    int node0 = blk * NPB;

    for (int i = tid; i < D * D; i += 256) Ws[i] = W[i];
    const float4* xsrc = (const float4*)x;
    for (int i = tid; i < NPB * 16; i += 256) {
        int nloc = i >> 4, kq = i & 15;
        int n = node0 + nloc;
        float4 v = (n < NN) ? xsrc[n * 16 + kq] : make_float4(0.f, 0.f, 0.f, 0.f);
        ((float4*)xr)[nloc * 17 + kq] = v;
    }
    __syncthreads();

    int nq = tid >> 4, fq = tid & 15;
    int nb = nq * 4;
    float4 acc[4];
#pragma unroll
    for (int i = 0; i < 4; i++) acc[i] = make_float4(0.f, 0.f, 0.f, 0.f);

    const float4* ws4 = (const float4*)Ws;
    const float4* xr4 = (const float4*)xr;
#pragma unroll 4
    for (int kq = 0; kq < 16; kq++) {
        float4 w0 = ws4[(kq * 4 + 0) * 16 + fq];
        float4 w1 = ws4[(kq * 4 + 1) * 16 + fq];
        float4 w2 = ws4[(kq * 4 + 2) * 16 + fq];
        float4 w3 = ws4[(kq * 4 + 3) * 16 + fq];
#pragma unroll
        for (int i = 0; i < 4; i++) {
            float4 xv = xr4[(nb + i) * 17 + kq];
            acc[i].x = fmaf(xv.x, w0.x, acc[i].x); acc[i].y = fmaf(xv.x, w0.y, acc[i].y);
            acc[i].z = fmaf(xv.x, w0.z, acc[i].z); acc[i].w = fmaf(xv.x, w0.w, acc[i].w);
            acc[i].x = fmaf(xv.y, w1.x, acc[i].x); acc[i].y = fmaf(xv.y, w1.y, acc[i].y);
            acc[i].z = fmaf(xv.y, w1.z, acc[i].z); acc[i].w = fmaf(xv.y, w1.w, acc[i].w);
            acc[i].x = fmaf(xv.z, w2.x, acc[i].x); acc[i].y = fmaf(xv.z, w2.y, acc[i].y);
            acc[i].z = fmaf(xv.z, w2.z, acc[i].z); acc[i].w = fmaf(xv.z, w2.w, acc[i].w);
            acc[i].x = fmaf(xv.w, w3.x, acc[i].x); acc[i].y = fmaf(xv.w, w3.y, acc[i].y);
            acc[i].z = fmaf(xv.w, w3.z, acc[i].z); acc[i].w = fmaf(xv.w, w3.w, acc[i].w);
        }
    }

    float4 asv = ((const float4*)as)[fq];
    float4 adv = ((const float4*)ad)[fq];
#pragma unroll
    for (int i = 0; i < 4; i++) {
        int n = node0 + nb + i;
        float vs = acc[i].x * asv.x + acc[i].y * asv.y + acc[i].z * asv.z + acc[i].w * asv.w;
        float vd = acc[i].x * adv.x + acc[i].y * adv.y + acc[i].z * adv.z + acc[i].w * adv.w;
        vs += __shfl_xor_sync(0xffffffffu, vs, 1);
        vs += __shfl_xor_sync(0xffffffffu, vs, 2);
        vd += __shfl_xor_sync(0xffffffffu, vd, 1);
        vd += __shfl_xor_sync(0xffffffffu, vd, 2);
        if (n < NN) {
            union { __half2 h[2]; uint2 u; } cv;
            cv.h[0] = __floats2half2_rn(acc[i].x, acc[i].y);
            cv.h[1] = __floats2half2_rn(acc[i].z, acc[i].w);
            ((uint2*)g_xsh1)[n * 16 + fq] = cv.u;
            if ((fq & 3) == 0) {
                g_as1[n * 4 + (fq >> 2)] = vs;
                g_ad1[n * 4 + (fq >> 2)] = vd;
            }
        }
    }
}

#define GEMM_SMEM (D * D + NPB * 68)

// ---------------- stats (+ wedot precompute in extra block) ------------------
__global__ void k_stats(const int* __restrict__ dst, const float* __restrict__ ea,
                        const float* __restrict__ We1, const float* __restrict__ ae1,
                        const float* __restrict__ We2, const float* __restrict__ ae2) {
    if (blockIdx.x == STATS_BLKS) {
        if (threadIdx.x < 2 * H) {
            int h = threadIdx.x & (H - 1);
            const float* We = (threadIdx.x < H) ? We1 : We2;
            const float* ae = (threadIdx.x < H) ? ae1 : ae2;
            float s = 0.f;
#pragma unroll
            for (int c = 0; c < C; c++) s += We[h * C + c] * ae[h * C + c];
            ((float*)g_wedot4)[threadIdx.x] = s;
        }
        return;
    }
    int e = blockIdx.x * 256 + threadIdx.x;   // EE = 6250*256 exact
    int d = dst[e];
    atomicAdd(&g_icnt[d], 1);
    atomicAdd(&g_loop[d], ea[e]);
}

// ---------------- 3-kernel multi-block exclusive scan of (deg = cnt + 1) -----
__global__ void k_scan1() {
    __shared__ int wsum[SB / 32];
    int b = blockIdx.x, t = threadIdx.x;
    int i = b * SB + t;
    int v = (i < NN) ? (g_icnt[i] + 1) : 0;
    int x = v;
#pragma unroll
    for (int o = 1; o < 32; o <<= 1) {
        int y = __shfl_up_sync(0xffffffffu, x, o);
        if ((t & 31) >= o) x += y;
    }
    if ((t & 31) == 31) wsum[t >> 5] = x;
    __syncthreads();
    if (t < 32) {
        int y = (t < SB / 32) ? wsum[t] : 0;
#pragma unroll
        for (int o = 1; o < 32; o <<= 1) {
            int z = __shfl_up_sync(0xffffffffu, y, o);
            if (t >= o) y += z;
        }
        if (t < SB / 32) wsum[t] = y;
    }
    __syncthreads();
    int off = (t >= 32) ? wsum[(t >> 5) - 1] : 0;
    int incl = x + off;
    if (i < NN) g_rowptr[i] = incl - v;
    if (t == SB - 1) g_bsum[b] = incl;
}

__global__ void k_scan2() {   // 1 block, 128 threads (NB <= 128)
    __shared__ int wsum[4];
    int t = threadIdx.x;
    int v = (t < NB) ? g_bsum[t] : 0;
    int x = v;
#pragma unroll
    for (int o = 1; o < 32; o <<= 1) {
        int y = __shfl_up_sync(0xffffffffu, x, o);
        if ((t & 31) >= o) x += y;
    }
    if ((t & 31) == 31) wsum[t >> 5] = x;
    __syncthreads();
    if (t < 32) {
        int y = (t < 4) ? wsum[t] : 0;
#pragma unroll
        for (int o = 1; o < 4; o <<= 1) {
            int z = __shfl_up_sync(0xffffffffu, y, o);
            if (t >= o) y += z;
        }
        if (t < 4) wsum[t] = y;
    }
    __syncthreads();
    int off = (t >= 32) ? wsum[(t >> 5) - 1] : 0;
    int incl = x + off;
    if (t < NB) g_boff[t] = incl - v;
    if (t == 127) g_rowptr[NN] = incl;
}

__global__ void k_scan3() {
    int b = blockIdx.x;
    int i = b * SB + threadIdx.x;
    if (i < NN) {
        int r = g_rowptr[i] + g_boff[b];
        g_rowptr[i] = r;
        g_cursor[i] = r;
    }
}

// ---------------- fused launch: gemm layer-1 blocks + scatter blocks ---------
__global__ void k_scatgemm(const int* __restrict__ src, const int* __restrict__ dst,
                           const float* __restrict__ ea,
                           const float* __restrict__ x, const float* __restrict__ W1,
                           const float* __restrict__ as1, const float* __restrict__ ad1) {
    __shared__ float smem[GEMM_SMEM];
    if (blockIdx.x < GEMM_BLKS) {
        gemm_body(x, W1, as1, ad1, blockIdx.x, smem);
        return;
    }
    int e = (blockIdx.x - GEMM_BLKS) * 256 + threadIdx.x;
    if (e >= E2) return;
    if (e < EE) {
        int d = dst[e];
        int pos = atomicAdd(&g_cursor[d], 1);
        g_epack[pos] = make_int2(src[e], __float_as_int(ea[e]));
    } else {
        int n = e - EE;
        int pos = atomicAdd(&g_cursor[n], 1);
        float la = g_loop[n] / fmaxf((float)g_icnt[n], 1.0f);
        g_epack[pos] = make_int2(n, __float_as_int(la));
    }
}

// ---------------- fused: edge-softmax agg + bias + resid + LN + ELU ----------
//   layer 0: + gemm2 epilogue (h1@W2 -> g_xsh2, g_as2, g_ad2) + h1 write
//   layer 1: + output head (y . Wout + bout -> out) + tail zeroing blocks
// warp per node; 8 nodes per 256-thread block; lane owns features 2l, 2l+1
__global__ void k_agg(const float* __restrict__ resid_ext, const float* __restrict__ bias,
                      const float* __restrict__ gamma, const float* __restrict__ beta,
                      const float* __restrict__ W2,
                      const float* __restrict__ as2w, const float* __restrict__ ad2w,
                      const float* __restrict__ Wout, const float* __restrict__ bout,
                      float* __restrict__ out, int layer) {
    if (layer == 1 && blockIdx.x >= AGG_BLKS) {   // tail zeroing for next call
        int i = (blockIdx.x - AGG_BLKS) * 256 + threadIdx.x;
        if (i < NN) { g_icnt[i] = 0; g_loop[i] = 0.f; }
        return;
    }

    const float* resid = (layer == 0) ? resid_ext : g_h1;
    const __half2* xsh = (layer == 0) ? g_xsh1 : g_xsh2;
    const float4* as4 = (const float4*)((layer == 0) ? g_as1 : g_as2);
    const float4* ad4 = (const float4*)((layer == 0) ? g_ad1 : g_ad2);

    __shared__ float sw[8][32 * 4];   // [warp][edge*4+head]
    __shared__ float Ws2[D * D];      // layer 0 only

    int t = threadIdx.x;
    if (layer == 0)
        for (int i = t; i < D * D; i += 256) Ws2[i] = W2[i];
    __syncthreads();

    int wid = t >> 5, l = t & 31;
    int n = blockIdx.x * 8 + wid;     // NN == 8*6250 exact
    int h = l >> 3;
    float* swp = sw[wid];

    float4 wd = g_wedot4[layer];
    float4 adn = ad4[n];
    int s0 = g_rowptr[n], s1 = g_rowptr[n + 1];

    float accx = 0.f, accy = 0.f, den = 0.f;

    for (int base = s0; base < s1; base += 32) {
        int p = base + l;
        int m = min(32, s1 - base);
        int sl = 0;
        if (p < s1) {
            int2 e = g_epack[p];
            sl = e.x;
            float eav = __int_as_float(e.y);
            float4 a4 = as4[sl];
            float a0 = a4.x + adn.x + eav * wd.x; a0 = (a0 > 0.f) ? a0 : 0.2f * a0;
            float a1 = a4.y + adn.y + eav * wd.y; a1 = (a1 > 0.f) ? a1 : 0.2f * a1;
            float a2 = a4.z + adn.z + eav * wd.z; a2 = (a2 > 0.f) ? a2 : 0.2f * a2;
            float a3 = a4.w + adn.w + eav * wd.w; a3 = (a3 > 0.f) ? a3 : 0.2f * a3;
            ((float4*)swp)[l] = make_float4(__expf(a0), __expf(a1), __expf(a2), __expf(a3));
        }
        __syncwarp();
#pragma unroll 4
        for (int e = 0; e < m; e++) {
            int s = __shfl_sync(0xffffffffu, sl, e);
            float w = swp[e * 4 + h];
            float2 xv = __half22float2(xsh[s * 32 + l]);
            accx = fmaf(w, xv.x, accx);
            accy = fmaf(w, xv.y, accy);
            den += w;
        }
        __syncwarp();
    }

    float inv = 1.0f / (den + 1e-16f);
    float2 b2 = ((const float2*)bias)[l];
    float2 r2 = ((const float2*)resid)[n * 32 + l];
    float vx = accx * inv + b2.x + r2.x;
    float vy = accy * inv + b2.y + r2.y;

    float s = vx + vy;
#pragma unroll
    for (int o = 16; o; o >>= 1) s += __shfl_xor_sync(0xffffffffu, s, o);
    float mean = s * (1.0f / 64.0f);
    float dx = vx - mean, dy = vy - mean;
    float q = dx * dx + dy * dy;
#pragma unroll
    for (int o = 16; o; o >>= 1) q += __shfl_xor_sync(0xffffffffu, q, o);
    float rstd = rsqrtf(q * (1.0f / 64.0f) + 1e-5f);

    float2 gm = ((const float2*)gamma)[l];
    float2 bt = ((const float2*)beta)[l];
    float yx = dx * rstd * gm.x + bt.x;
    float yy = dy * rstd * gm.y + bt.y;
    yx = (yx > 0.f) ? yx : (__expf(yx) - 1.0f);
    yy = (yy > 0.f) ? yy : (__expf(yy) - 1.0f);

    if (layer == 0) {
        // residual for layer 2
        ((float2*)g_h1)[n * 32 + l] = make_float2(yx, yy);
        // fused gemm2: xs2[n] = h1[n] @ W2 (row-local, shfl-broadcast)
        float ax = 0.f, ay = 0.f;
        const float2* w2f = (const float2*)Ws2;
#pragma unroll 8
        for (int m2 = 0; m2 < 32; m2++) {
            float hx = __shfl_sync(0xffffffffu, yx, m2);
            float hy = __shfl_sync(0xffffffffu, yy, m2);
            float2 w0 = w2f[(2 * m2) * 32 + l];
            float2 w1 = w2f[(2 * m2 + 1) * 32 + l];
            ax = fmaf(hx, w0.x, fmaf(hy, w1.x, ax));
            ay = fmaf(hx, w0.y, fmaf(hy, w1.y, ay));
        }
        g_xsh2[n * 32 + l] = __floats2half2_rn(ax, ay);
        // attention dots for layer 2
        float2 asw = ((const float2*)as2w)[l];
        float2 adw = ((const float2*)ad2w)[l];
        float vs = ax * asw.x + ay * asw.y;
        float vd = ax * adw.x + ay * adw.y;
        vs += __shfl_xor_sync(0xffffffffu, vs, 1);
        vs += __shfl_xor_sync(0xffffffffu, vs, 2);
        vs += __shfl_xor_sync(0xffffffffu, vs, 4);
        vd += __shfl_xor_sync(0xffffffffu, vd, 1);
        vd += __shfl_xor_sync(0xffffffffu, vd, 2);
        vd += __shfl_xor_sync(0xffffffffu, vd, 4);
        if ((l & 7) == 0) {
            g_as2[n * 4 + h] = vs;
            g_ad2[n * 4 + h] = vd;
        }
    } else {
        // fused output head
        float2 wo = ((const float2*)Wout)[l];
        float p = yx * wo.x + yy * wo.y;
#pragma unroll
        for (int o = 16; o; o >>= 1) p += __shfl_xor_sync(0xffffffffu, p, o);
        if (l == 0) out[n] = p + bout[0];
    }
}

// ---------------- launch ------------------------------------------------------
extern "C" void kernel_launch(void* const* d_in, const int* in_sizes, int n_in,
                              void* d_out, int out_size) {
    const float* x    = (const float*)d_in[0];
    const int*   ei   = (const int*)d_in[1];       // [2,E]: src then dst
    const float* ea   = (const float*)d_in[3];
    const float* W1   = (const float*)d_in[4];
    const float* as1  = (const float*)d_in[5];
    const float* ad1  = (const float*)d_in[6];
    const float* We1  = (const float*)d_in[7];
    const float* ae1  = (const float*)d_in[8];
    const float* b1   = (const float*)d_in[9];
    const float* W2   = (const float*)d_in[10];
    const float* as2  = (const float*)d_in[11];
    const float* ad2  = (const float*)d_in[12];
    const float* We2  = (const float*)d_in[13];
    const float* ae2  = (const float*)d_in[14];
    const float* b2   = (const float*)d_in[15];
    const float* g1   = (const float*)d_in[16];
    const float* be1  = (const float*)d_in[17];
    const float* g2   = (const float*)d_in[18];
    const float* be2  = (const float*)d_in[19];
    const float* Wout = (const float*)d_in[20];
    const float* bout = (const float*)d_in[21];
    float* out = (float*)d_out;

    const int* srcp = ei;
    const int* dstp = ei + EE;

    k_stats<<<STATS_BLKS + 1, 256>>>(dstp, ea, We1, ae1, We2, ae2);
    k_scan1<<<NB, SB>>>();
    k_scan2<<<1, 128>>>();
    k_scan3<<<NB, SB>>>();
    // gemm layer-1 co-scheduled with CSR scatter (independent work)
    k_scatgemm<<<GEMM_BLKS + SCAT_BLKS, 256>>>(srcp, dstp, ea, x, W1, as1, ad1);
    // agg layer 1 (+ fused gemm2 epilogue)
    k_agg<<<AGG_BLKS, 256>>>(x, b1, g1, be1, W2, as2, ad2, Wout, bout, out, 0);
    // agg layer 2 (+ fused output head + tail zeroing)
    k_agg<<<AGG_BLKS + ZERO_BLKS, 256>>>(x, b2, g2, be2, W2, as2, ad2, Wout, bout, out, 1);
}

// round 16
// speedup vs baseline: 1.0743x; 1.0743x over previous
#include <cuda_runtime.h>
#include <cuda_fp16.h>

#define NN 50000
#define EE 1600000
#define E2 (EE + NN)
#define H 4
#define C 16
#define D 64
#define SB 512
#define NB ((NN + SB - 1) / SB)        // 98
#define STATS_BLKS (EE / 256)          // 6250 exact
#define SCAT_BLKS ((E2 + 255) / 256)   // 6446
#define NPB 64
#define GEMM_BLKS ((NN + NPB - 1) / NPB)  // 782
#define OUT_BLKS (NN / 8)              // 6250
#define ZERO_BLKS 196

// ---------------- scratch (static device globals; no allocation) -------------
// g_icnt / g_loop are zeroed at the TAIL of each call (k_out), so every call
// finds them zero. Module load zero-initializes for the first call.
__device__ int   g_icnt[NN];
__device__ float g_loop[NN];
__device__ int   g_rowptr[NN + 1];
__device__ int   g_cursor[NN];
__device__ int   g_bsum[NB];
__device__ int2  g_epack[E2];                         // {src, float_bits(ea)}
__device__ __align__(16) __half2 g_xsh[NN * 32];      // messages (fp16 payload)
__device__ __align__(16) float g_as[NN * H];
__device__ __align__(16) float g_ad[NN * H];
__device__ __align__(16) float g_h1[NN * D];
__device__ __align__(16) float g_h2[NN * D];
__device__ float4 g_wedot4[2];

// ---------------- GEMM body: xs = x @ W (fp16 out) + per-head attn dots ------
// 256 threads: 16 node-quads x 16 feature-quads; thread owns 4x4 outputs.
__device__ __forceinline__ void gemm_body(
    const float* __restrict__ x, const float* __restrict__ W,
    const float* __restrict__ as, const float* __restrict__ ad,
    int blk, float* smem) {
    float* Ws = smem;                 // D*D floats
    float* xr = smem + D * D;         // NPB*68 floats (17 float4 stride)
    int tid = threadIdx.x;
    int node0 = blk * NPB;

    for (int i = tid; i < D * D; i += 256) Ws[i] = W[i];
    const float4* xsrc = (const float4*)x;
    for (int i = tid; i < NPB * 16; i += 256) {
        int nloc = i >> 4, kq = i & 15;
        int n = node0 + nloc;
        float4 v = (n < NN) ? xsrc[n * 16 + kq] : make_float4(0.f, 0.f, 0.f, 0.f);
        ((float4*)xr)[nloc * 17 + kq] = v;
    }
    __syncthreads();

    int nq = tid >> 4, fq = tid & 15;
    int nb = nq * 4;
    float4 acc[4];
#pragma unroll
    for (int i = 0; i < 4; i++) acc[i] = make_float4(0.f, 0.f, 0.f, 0.f);

    const float4* ws4 = (const float4*)Ws;
    const float4* xr4 = (const float4*)xr;
#pragma unroll 4
    for (int kq = 0; kq < 16; kq++) {
        float4 w0 = ws4[(kq * 4 + 0) * 16 + fq];
        float4 w1 = ws4[(kq * 4 + 1) * 16 + fq];
        float4 w2 = ws4[(kq * 4 + 2) * 16 + fq];
        float4 w3 = ws4[(kq * 4 + 3) * 16 + fq];
#pragma unroll
        for (int i = 0; i < 4; i++) {
            float4 xv = xr4[(nb + i) * 17 + kq];
            acc[i].x = fmaf(xv.x, w0.x, acc[i].x); acc[i].y = fmaf(xv.x, w0.y, acc[i].y);
            acc[i].z = fmaf(xv.x, w0.z, acc[i].z); acc[i].w = fmaf(xv.x, w0.w, acc[i].w);
            acc[i].x = fmaf(xv.y, w1.x, acc[i].x); acc[i].y = fmaf(xv.y, w1.y, acc[i].y);
            acc[i].z = fmaf(xv.y, w1.z, acc[i].z); acc[i].w = fmaf(xv.y, w1.w, acc[i].w);
            acc[i].x = fmaf(xv.z, w2.x, acc[i].x); acc[i].y = fmaf(xv.z, w2.y, acc[i].y);
            acc[i].z = fmaf(xv.z, w2.z, acc[i].z); acc[i].w = fmaf(xv.z, w2.w, acc[i].w);
            acc[i].x = fmaf(xv.w, w3.x, acc[i].x); acc[i].y = fmaf(xv.w, w3.y, acc[i].y);
            acc[i].z = fmaf(xv.w, w3.z, acc[i].z); acc[i].w = fmaf(xv.w, w3.w, acc[i].w);
        }
    }

    float4 asv = ((const float4*)as)[fq];
    float4 adv = ((const float4*)ad)[fq];
#pragma unroll
    for (int i = 0; i < 4; i++) {
        int n = node0 + nb + i;
        float vs = acc[i].x * asv.x + acc[i].y * asv.y + acc[i].z * asv.z + acc[i].w * asv.w;
        float vd = acc[i].x * adv.x + acc[i].y * adv.y + acc[i].z * adv.z + acc[i].w * adv.w;
        vs += __shfl_xor_sync(0xffffffffu, vs, 1);
        vs += __shfl_xor_sync(0xffffffffu, vs, 2);
        vd += __shfl_xor_sync(0xffffffffu, vd, 1);
        vd += __shfl_xor_sync(0xffffffffu, vd, 2);
        if (n < NN) {
            union { __half2 h[2]; uint2 u; } cv;
            cv.h[0] = __floats2half2_rn(acc[i].x, acc[i].y);
            cv.h[1] = __floats2half2_rn(acc[i].z, acc[i].w);
            ((uint2*)g_xsh)[n * 16 + fq] = cv.u;
            if ((fq & 3) == 0) {
                g_as[n * 4 + (fq >> 2)] = vs;
                g_ad[n * 4 + (fq >> 2)] = vd;
            }
        }
    }
}

#define GEMM_SMEM (D * D + NPB * 68)

// ---------------- stats (+ wedot precompute in extra block) ------------------
__global__ void k_stats(const int* __restrict__ dst, const float* __restrict__ ea,
                        const float* __restrict__ We1, const float* __restrict__ ae1,
                        const float* __restrict__ We2, const float* __restrict__ ae2) {
    if (blockIdx.x == STATS_BLKS) {
        if (threadIdx.x < 2 * H) {
            int h = threadIdx.x & (H - 1);
            const float* We = (threadIdx.x < H) ? We1 : We2;
            const float* ae = (threadIdx.x < H) ? ae1 : ae2;
            float s = 0.f;
#pragma unroll
            for (int c = 0; c < C; c++) s += We[h * C + c] * ae[h * C + c];
            ((float*)g_wedot4)[threadIdx.x] = s;
        }
        return;
    }
    int e = blockIdx.x * 256 + threadIdx.x;   // EE = 6250*256 exact
    int d = dst[e];
    atomicAdd(&g_icnt[d], 1);
    atomicAdd(&g_loop[d], ea[e]);
}

// ---------------- scan pass 1: block-local exclusive scan of (cnt + 1) -------
__global__ void k_scan1() {
    __shared__ int wsum[SB / 32];
    int b = blockIdx.x, t = threadIdx.x;
    int i = b * SB + t;
    int v = (i < NN) ? (g_icnt[i] + 1) : 0;
    int x = v;
#pragma unroll
    for (int o = 1; o < 32; o <<= 1) {
        int y = __shfl_up_sync(0xffffffffu, x, o);
        if ((t & 31) >= o) x += y;
    }
    if ((t & 31) == 31) wsum[t >> 5] = x;
    __syncthreads();
    if (t < 32) {
        int y = (t < SB / 32) ? wsum[t] : 0;
#pragma unroll
        for (int o = 1; o < 32; o <<= 1) {
            int z = __shfl_up_sync(0xffffffffu, y, o);
            if (t >= o) y += z;
        }
        if (t < SB / 32) wsum[t] = y;
    }
    __syncthreads();
    int off = (t >= 32) ? wsum[(t >> 5) - 1] : 0;
    int incl = x + off;
    if (i < NN) g_rowptr[i] = incl - v;
    if (t == SB - 1) g_bsum[b] = incl;
}

// ---------------- scan pass 2 (merged): each block derives its own prefix ----
__global__ void k_scan23() {
    __shared__ int spref;
    int b = blockIdx.x, t = threadIdx.x;
    if (t < 32) {
        int s = 0;
        for (int i = t; i < b; i += 32) s += g_bsum[i];
#pragma unroll
        for (int o = 16; o; o >>= 1) s += __shfl_xor_sync(0xffffffffu, s, o);
        if (t == 0) spref = s;
    }
    __syncthreads();
    int i = b * SB + t;
    if (i < NN) {
        int r = g_rowptr[i] + spref;
        g_rowptr[i] = r;
        g_cursor[i] = r;
    }
    if (b == 0 && t == 0) g_rowptr[NN] = E2;   // total degree is a constant
}

// ---------------- fused launch: gemm layer-1 blocks + scatter blocks ---------
__global__ void k_scatgemm(const int* __restrict__ src, const int* __restrict__ dst,
                           const float* __restrict__ ea,
                           const float* __restrict__ x, const float* __restrict__ W1,
                           const float* __restrict__ as1, const float* __restrict__ ad1) {
    __shared__ float smem[GEMM_SMEM];
    if (blockIdx.x < GEMM_BLKS) {
        gemm_body(x, W1, as1, ad1, blockIdx.x, smem);
        return;
    }
    int e = (blockIdx.x - GEMM_BLKS) * 256 + threadIdx.x;
    if (e >= E2) return;
    if (e < EE) {
        int d = dst[e];
        int pos = atomicAdd(&g_cursor[d], 1);
        g_epack[pos] = make_int2(src[e], __float_as_int(ea[e]));
    } else {
        int n = e - EE;
        int pos = atomicAdd(&g_cursor[n], 1);
        float la = g_loop[n] / fmaxf((float)g_icnt[n], 1.0f);
        g_epack[pos] = make_int2(n, __float_as_int(la));
    }
}

// ---------------- gemm layer-2 standalone ------------------------------------
__global__ void k_gemm2(const float* __restrict__ W2,
                        const float* __restrict__ as2, const float* __restrict__ ad2) {
    __shared__ float smem[GEMM_SMEM];
    gemm_body(g_h1, W2, as2, ad2, blockIdx.x, smem);
}

// ---------------- fused: edge-softmax aggregate + bias + residual + LN + ELU -
// warp per node; 8 nodes per 256-thread block; lane owns features 2l, 2l+1
__global__ void k_agg(const float* __restrict__ resid_ext, const float* __restrict__ bias,
                      const float* __restrict__ gamma, const float* __restrict__ beta,
                      int layer) {
    const float* resid = (layer == 0) ? resid_ext : g_h1;
    float* out = (layer == 0) ? g_h1 : g_h2;
    const float4* as4 = (const float4*)g_as;
    const float4* ad4 = (const float4*)g_ad;

    __shared__ float sw[8][32 * 4];   // [warp][edge*4+head]

    int t = threadIdx.x;
    int wid = t >> 5, l = t & 31;
    int n = blockIdx.x * 8 + wid;     // NN == 8*6250 exact
    int h = l >> 3;
    float* swp = sw[wid];

    float4 wd = g_wedot4[layer];
    float4 adn = ad4[n];
    int s0 = g_rowptr[n], s1 = g_rowptr[n + 1];

    float accx = 0.f, accy = 0.f, den = 0.f;

    for (int base = s0; base < s1; base += 32) {
        int p = base + l;
        int m = min(32, s1 - base);
        int sl = 0;
        if (p < s1) {
            int2 e = g_epack[p];
            sl = e.x;
            float eav = __int_as_float(e.y);
            float4 a4 = as4[sl];
            float a0 = a4.x + adn.x + eav * wd.x; a0 = (a0 > 0.f) ? a0 : 0.2f * a0;
            float a1 = a4.y + adn.y + eav * wd.y; a1 = (a1 > 0.f) ? a1 : 0.2f * a1;
            float a2 = a4.z + adn.z + eav * wd.z; a2 = (a2 > 0.f) ? a2 : 0.2f * a2;
            float a3 = a4.w + adn.w + eav * wd.w; a3 = (a3 > 0.f) ? a3 : 0.2f * a3;
            ((float4*)swp)[l] = make_float4(__expf(a0), __expf(a1), __expf(a2), __expf(a3));
        }
        __syncwarp();
#pragma unroll 4
        for (int e = 0; e < m; e++) {
            int s = __shfl_sync(0xffffffffu, sl, e);
            float w = swp[e * 4 + h];
            float2 xv = __half22float2(g_xsh[s * 32 + l]);
            accx = fmaf(w, xv.x, accx);
            accy = fmaf(w, xv.y, accy);
            den += w;
        }
        __syncwarp();
    }

    float inv = 1.0f / (den + 1e-16f);
    float2 b2 = ((const float2*)bias)[l];
    float2 r2 = ((const float2*)resid)[n * 32 + l];
    float vx = accx * inv + b2.x + r2.x;
    float vy = accy * inv + b2.y + r2.y;

    float s = vx + vy;
#pragma unroll
    for (int o = 16; o; o >>= 1) s += __shfl_xor_sync(0xffffffffu, s, o);
    float mean = s * (1.0f / 64.0f);
    float dx = vx - mean, dy = vy - mean;
    float q = dx * dx + dy * dy;
#pragma unroll
    for (int o = 16; o; o >>= 1) q += __shfl_xor_sync(0xffffffffu, q, o);
    float rstd = rsqrtf(q * (1.0f / 64.0f) + 1e-5f);

    float2 gm = ((const float2*)gamma)[l];
    float2 bt = ((const float2*)beta)[l];
    float yx = dx * rstd * gm.x + bt.x;
    float yy = dy * rstd * gm.y + bt.y;
    yx = (yx > 0.f) ? yx : (__expf(yx) - 1.0f);
    yy = (yy > 0.f) ? yy : (__expf(yy) - 1.0f);
    ((float2*)out)[n * 32 + l] = make_float2(yx, yy);
}

// ---------------- output head + tail zeroing of per-call accumulators --------
__global__ void k_out(const float* __restrict__ Wout, const float* __restrict__ bout,
                      float* __restrict__ out) {
    if (blockIdx.x >= OUT_BLKS) {
        int i = (blockIdx.x - OUT_BLKS) * 256 + threadIdx.x;
        if (i < NN) { g_icnt[i] = 0; g_loop[i] = 0.f; }
        return;
    }
    __shared__ float w[D];
    int tid = threadIdx.x;
    if (tid < D) w[tid] = Wout[tid];
    __syncthreads();
    int warp = tid >> 5, lane = tid & 31;
    int n = blockIdx.x * 8 + warp;
    float v = g_h2[n * D + lane] * w[lane] + g_h2[n * D + lane + 32] * w[lane + 32];
#pragma unroll
    for (int o = 16; o; o >>= 1) v += __shfl_down_sync(0xffffffffu, v, o);
    if (lane == 0) out[n] = v + bout[0];
}

// ---------------- launch ------------------------------------------------------
extern "C" void kernel_launch(void* const* d_in, const int* in_sizes, int n_in,
                              void* d_out, int out_size) {
    const float* x    = (const float*)d_in[0];
    const int*   ei   = (const int*)d_in[1];       // [2,E]: src then dst
    const float* ea   = (const float*)d_in[3];
    const float* W1   = (const float*)d_in[4];
    const float* as1  = (const float*)d_in[5];
    const float* ad1  = (const float*)d_in[6];
    const float* We1  = (const float*)d_in[7];
    const float* ae1  = (const float*)d_in[8];
    const float* b1   = (const float*)d_in[9];
    const float* W2   = (const float*)d_in[10];
    const float* as2  = (const float*)d_in[11];
    const float* ad2  = (const float*)d_in[12];
    const float* We2  = (const float*)d_in[13];
    const float* ae2  = (const float*)d_in[14];
    const float* b2   = (const float*)d_in[15];
    const float* g1   = (const float*)d_in[16];
    const float* be1  = (const float*)d_in[17];
    const float* g2   = (const float*)d_in[18];
    const float* be2  = (const float*)d_in[19];
    const float* Wout = (const float*)d_in[20];
    const float* bout = (const float*)d_in[21];
    float* out = (float*)d_out;

    const int* srcp = ei;
    const int* dstp = ei + EE;

    k_stats<<<STATS_BLKS + 1, 256>>>(dstp, ea, We1, ae1, We2, ae2);
    k_scan1<<<NB, SB>>>();
    k_scan23<<<NB, SB>>>();
    // gemm layer-1 co-scheduled with CSR scatter (independent work); idx 3 -> profiled
    k_scatgemm<<<GEMM_BLKS + SCAT_BLKS, 256>>>(srcp, dstp, ea, x, W1, as1, ad1);
    k_agg<<<NN / 8, 256>>>(x, b1, g1, be1, 0);
    k_gemm2<<<GEMM_BLKS, 256>>>(W2, as2, ad2);
    k_agg<<<NN / 8, 256>>>(x, b2, g2, be2, 1);
    k_out<<<OUT_BLKS + ZERO_BLKS, 256>>>(Wout, bout, out);
}